// round 7
// baseline (speedup 1.0000x reference)
#include <cuda_runtime.h>
#include <cuda_bf16.h>
#include <stdint.h>

#define BATCH 4
#define SEQ_Q 4096
#define SEQ_V 4096
#define HDIM  64

#define TQ 64                   // q rows per CTA
#define TN 128                  // kv rows per tile
#define KVSPLIT 4
#define KVCHUNK (SEQ_V / KVSPLIT)       // 1024
#define TILES_PER_CTA (KVCHUNK / TN)    // 8
#define NT 128                  // 4 warps

#define SWZ(x) ((uint32_t)(x) ^ ((((uint32_t)(x)) >> 3) & 0x70u))

// smem: QH[8K] | QL[8K] | V0 hi/lo[32K] | V1 hi/lo[32K] = 80K
#define SM_QH 0
#define SM_QL 8192
#define SM_V  16384
#define SMEM_TOTAL 81920

// prepacked bf16 hi/lo (pairs)
__device__ uint32_t g_qh[(size_t)BATCH * SEQ_Q * HDIM / 2];
__device__ uint32_t g_ql[(size_t)BATCH * SEQ_Q * HDIM / 2];
__device__ uint32_t g_vh[(size_t)BATCH * SEQ_V * HDIM / 2];
__device__ uint32_t g_vl[(size_t)BATCH * SEQ_V * HDIM / 2];
// cross-CTA accumulators
__device__ float g_oacc[(size_t)BATCH * SEQ_Q * HDIM];
__device__ float g_lacc[(size_t)BATCH * SEQ_Q];

static __device__ __forceinline__ uint32_t smem_u32(const void* p) {
    uint32_t a;
    asm("{ .reg .u64 t; cvta.to.shared.u64 t, %1; cvt.u32.u64 %0, t; }" : "=r"(a) : "l"(p));
    return a;
}

// pack (x,y) -> bf16x2 hi word-pair + residual lo pair
static __device__ __forceinline__ void split_pack(float x, float y,
                                                  uint32_t& hi, uint32_t& lo) {
    asm("cvt.rn.bf16x2.f32 %0, %1, %2;" : "=r"(hi) : "f"(y), "f"(x));
    float xh = __uint_as_float(hi << 16);
    float yh = __uint_as_float(hi & 0xFFFF0000u);
    asm("cvt.rn.bf16x2.f32 %0, %1, %2;" : "=r"(lo) : "f"(y - yh), "f"(x - xh));
}

#define CP16(dst, src) \
    asm volatile("cp.async.cg.shared.global [%0], [%1], 16;" :: "r"(dst), "l"(src) : "memory")
#define CP_COMMIT() asm volatile("cp.async.commit_group;" ::: "memory")
#define CP_WAIT0()  asm volatile("cp.async.wait_group 0;" ::: "memory")
#define CP_WAIT1()  asm volatile("cp.async.wait_group 1;" ::: "memory")

#define LDSM4(R, addr) \
    asm volatile("ldmatrix.sync.aligned.m8n8.x4.shared.b16 {%0,%1,%2,%3}, [%4];" \
        : "=r"((R)[0]), "=r"((R)[1]), "=r"((R)[2]), "=r"((R)[3]) : "r"(addr))
#define LDSM4T(R, addr) \
    asm volatile("ldmatrix.sync.aligned.m8n8.x4.trans.shared.b16 {%0,%1,%2,%3}, [%4];" \
        : "=r"((R)[0]), "=r"((R)[1]), "=r"((R)[2]), "=r"((R)[3]) : "r"(addr))

#define MMA16816(C, A, b0_, b1_) \
    asm volatile("mma.sync.aligned.m16n8k16.row.col.f32.bf16.bf16.f32 " \
        "{%0,%1,%2,%3}, {%4,%5,%6,%7}, {%8,%9}, {%0,%1,%2,%3};" \
        : "+f"((C)[0]), "+f"((C)[1]), "+f"((C)[2]), "+f"((C)[3]) \
        : "r"((A)[0]), "r"((A)[1]), "r"((A)[2]), "r"((A)[3]), "r"(b0_), "r"(b1_))

#define REDV2(ptr, a, b) \
    asm volatile("red.global.add.v2.f32 [%0], {%1, %2};" :: "l"(ptr), "f"(a), "f"(b) : "memory")

static __device__ __forceinline__ float ex2f(float x) {
    float r; asm("ex2.approx.f32 %0, %1;" : "=f"(r) : "f"(x)); return r;
}

// ---------------- pre-pass: fp32 -> bf16 hi/lo packed; zero accumulators ----
__global__ void convert_kernel(const float* __restrict__ Q, const float* __restrict__ V) {
    int i = blockIdx.x * blockDim.x + threadIdx.x;   // float4 index, 0..262143
    const float L2E = 1.4426950408889634f;           // fold log2(e) into Q
    float4 q = ((const float4*)Q)[i];
    uint2 qh, ql;
    split_pack(q.x * L2E, q.y * L2E, qh.x, ql.x);
    split_pack(q.z * L2E, q.w * L2E, qh.y, ql.y);
    ((uint2*)g_qh)[i] = qh;
    ((uint2*)g_ql)[i] = ql;
    float4 v = ((const float4*)V)[i];
    uint2 vh, vl;
    split_pack(v.x, v.y, vh.x, vl.x);
    split_pack(v.z, v.w, vh.y, vl.y);
    ((uint2*)g_vh)[i] = vh;
    ((uint2*)g_vl)[i] = vl;
    ((float4*)g_oacc)[i] = make_float4(0.f, 0.f, 0.f, 0.f);
    if (i < (BATCH * SEQ_Q) / 4) ((float4*)g_lacc)[i] = make_float4(0.f, 0.f, 0.f, 0.f);
}

// ---------------- main attention kernel ----------------
static __device__ __forceinline__ void load_v_tile(uint32_t sb, int b, int kvrow,
                                                   int buf, int tid) {
    const char* gh = (const char*)g_vh + (size_t)(b * SEQ_V + kvrow) * HDIM * 2;
    const char* gl = (const char*)g_vl + (size_t)(b * SEQ_V + kvrow) * HDIM * 2;
    uint32_t vh = sb + SM_V + buf * 32768;
    uint32_t vl = vh + 16384;
#pragma unroll
    for (int i = 0; i < 8; i++) {
        uint32_t off = (uint32_t)(tid + i * NT) * 16;   // 1024 x 16B = 16KB
        CP16(vh + SWZ(off), gh + off);
        CP16(vl + SWZ(off), gl + off);
    }
}

__global__ __launch_bounds__(NT, 2)
void attn_mma_kernel()
{
    extern __shared__ char smem[];
    const uint32_t sb = smem_u32(smem);
    const int tid = threadIdx.x;
    const int l = tid & 31, w = tid >> 5;
    const int qt = blockIdx.x & 255;     // (b, q64)
    const int kc = blockIdx.x >> 8;      // kv chunk 0..3
    const int b = qt >> 6;
    const int qrow0 = (qt & 63) * TQ;    // within batch
    const int kv0 = kc * KVCHUNK;

    // ---- prologue: Q (hi+lo) + V tile 0
    {
        const char* gqh = (const char*)g_qh + (size_t)(b * SEQ_Q + qrow0) * HDIM * 2;
        const char* gql = (const char*)g_ql + (size_t)(b * SEQ_Q + qrow0) * HDIM * 2;
#pragma unroll
        for (int i = 0; i < 4; i++) {
            uint32_t off = (uint32_t)(tid + i * NT) * 16;   // 512 x 16B = 8KB
            CP16(sb + SM_QH + SWZ(off), gqh + off);
            CP16(sb + SM_QL + SWZ(off), gql + off);
        }
        load_v_tile(sb, b, kv0, 0, tid);
        CP_COMMIT();
        CP_WAIT0();
        __syncthreads();
    }

    // ---- Q A-fragments (per warp: rows w*16..w*16+15)
    uint32_t aqh[4][4], aql[4][4];
    {
        int qrow = w * 16 + (l & 15);
#pragma unroll
        for (int kk = 0; kk < 4; kk++) {
            uint32_t off = SWZ((uint32_t)qrow * 128 + kk * 32 + ((l >> 4) & 1) * 16);
            LDSM4(aqh[kk], sb + SM_QH + off);
            LDSM4(aql[kk], sb + SM_QL + off);
        }
    }

    float oc[8][4];
#pragma unroll
    for (int f = 0; f < 8; f++) { oc[f][0] = oc[f][1] = oc[f][2] = oc[f][3] = 0.f; }
    float lsum0 = 0.f, lsum1 = 0.f;

    for (int t = 0; t < TILES_PER_CTA; t++) {
        __syncthreads();
        if (t + 1 < TILES_PER_CTA) {
            load_v_tile(sb, b, kv0 + (t + 1) * TN, (t + 1) & 1, tid);
            CP_COMMIT();
            CP_WAIT1();
        } else {
            CP_WAIT0();
        }
        __syncthreads();

        const uint32_t vhb = sb + SM_V + (t & 1) * 32768;
        const uint32_t vlb = vhb + 16384;

        // ---- fused per-16kv-chunk: S -> exp -> pack -> PV
        // Chunks are independent; S-MMAs of chunk np+1 overlap exp/PV of np.
#pragma unroll
        for (int np = 0; np < 8; np++) {
            // S chunk accumulators (2 C-frags = 16 q x 16 kv)
            float s0[4] = {0.f, 0.f, 0.f, 0.f};
            float s1[4] = {0.f, 0.f, 0.f, 0.f};

#pragma unroll
            for (int kk = 0; kk < 4; kk++) {
                uint32_t off = SWZ((uint32_t)(16 * np + (l & 7) + ((l >> 4) & 1) * 8) * 128
                                   + kk * 32 + ((l >> 3) & 1) * 16);
                uint32_t bh[4], bl[4];
                LDSM4(bh, vhb + off);
                LDSM4(bl, vlb + off);
                MMA16816(s0, aqh[kk], bh[0], bh[1]);
                MMA16816(s1, aqh[kk], bh[2], bh[3]);
                MMA16816(s0, aqh[kk], bl[0], bl[1]);
                MMA16816(s1, aqh[kk], bl[2], bl[3]);
                MMA16816(s0, aql[kk], bh[0], bh[1]);
                MMA16816(s1, aql[kk], bh[2], bh[3]);
            }

            // softmax: p = 2^(s')  (no max subtraction; |s| bounded)
            s0[0] = ex2f(s0[0]); s0[1] = ex2f(s0[1]);
            s0[2] = ex2f(s0[2]); s0[3] = ex2f(s0[3]);
            s1[0] = ex2f(s1[0]); s1[1] = ex2f(s1[1]);
            s1[2] = ex2f(s1[2]); s1[3] = ex2f(s1[3]);
            lsum0 += s0[0] + s0[1] + s1[0] + s1[1];
            lsum1 += s0[2] + s0[3] + s1[2] + s1[3];

            // P -> bf16 hi/lo A-fragments
            uint32_t ah[4], al[4];
            split_pack(s0[0], s0[1], ah[0], al[0]);
            split_pack(s0[2], s0[3], ah[1], al[1]);
            split_pack(s1[0], s1[1], ah[2], al[2]);
            split_pack(s1[2], s1[3], ah[3], al[3]);

            // O += P . V  (bf16x3) for this 16-kv slab
#pragma unroll
            for (int dp = 0; dp < 4; dp++) {
                uint32_t off = SWZ((uint32_t)(16 * np + (l & 7) + ((l >> 3) & 1) * 8) * 128
                                   + dp * 32 + ((l >> 4) & 1) * 16);
                uint32_t vh[4], vl[4];
                LDSM4T(vh, vhb + off);
                LDSM4T(vl, vlb + off);
                MMA16816(oc[2 * dp],     ah, vh[0], vh[1]);
                MMA16816(oc[2 * dp + 1], ah, vh[2], vh[3]);
                MMA16816(oc[2 * dp],     ah, vl[0], vl[1]);
                MMA16816(oc[2 * dp + 1], ah, vl[2], vl[3]);
                MMA16816(oc[2 * dp],     al, vh[0], vh[1]);
                MMA16816(oc[2 * dp + 1], al, vh[2], vh[3]);
            }
        }
    }

    // ---- merge partials: row sums + unnormalized O (vector reductions)
    lsum0 += __shfl_xor_sync(0xFFFFFFFFu, lsum0, 1);
    lsum0 += __shfl_xor_sync(0xFFFFFFFFu, lsum0, 2);
    lsum1 += __shfl_xor_sync(0xFFFFFFFFu, lsum1, 1);
    lsum1 += __shfl_xor_sync(0xFFFFFFFFu, lsum1, 2);

    const int row0 = qrow0 + w * 16 + (l >> 2);
    float* oa = g_oacc + ((size_t)b * SEQ_Q + row0) * HDIM;
    float* ob = oa + 8 * HDIM;    // row0 + 8
    const int cb = 2 * (l & 3);
#pragma unroll
    for (int f = 0; f < 8; f++) {
        REDV2(oa + 8 * f + cb, oc[f][0], oc[f][1]);
        REDV2(ob + 8 * f + cb, oc[f][2], oc[f][3]);
    }
    if ((l & 3) == 0) {
        atomicAdd(g_lacc + (size_t)b * SEQ_Q + row0,     lsum0);
        atomicAdd(g_lacc + (size_t)b * SEQ_Q + row0 + 8, lsum1);
    }
}

// ---------------- normalize: O = acc / l ----------------
__global__ void normalize_kernel(float* __restrict__ O) {
    int i = blockIdx.x * blockDim.x + threadIdx.x;   // float4 units, 262144
    int row = i >> 4;                                // 16 float4 per row
    float inv = 1.0f / g_lacc[row];
    float4 v = ((const float4*)g_oacc)[i];
    ((float4*)O)[i] = make_float4(v.x * inv, v.y * inv, v.z * inv, v.w * inv);
}

extern "C" void kernel_launch(void* const* d_in, const int* in_sizes, int n_in,
                              void* d_out, int out_size)
{
    const float* Q = (const float*)d_in[0];
    const float* V = (const float*)d_in[1];
    float* O = (float*)d_out;

    convert_kernel<<<(BATCH * SEQ_Q * HDIM / 4) / 256, 256>>>(Q, V);

    cudaFuncSetAttribute(attn_mma_kernel,
                         cudaFuncAttributeMaxDynamicSharedMemorySize, SMEM_TOTAL);
    attn_mma_kernel<<<256 * KVSPLIT, NT, SMEM_TOTAL>>>();

    normalize_kernel<<<(BATCH * SEQ_Q * HDIM / 4) / 256, 256>>>(O);
}

// round 8
// speedup vs baseline: 1.0480x; 1.0480x over previous
#include <cuda_runtime.h>
#include <cuda_bf16.h>
#include <stdint.h>

#define BATCH 4
#define SEQ_Q 4096
#define SEQ_V 4096
#define HDIM  64

#define TQ 64                   // q rows per CTA
#define TN 128                  // kv rows per tile
#define KVSPLIT 4
#define KVCHUNK (SEQ_V / KVSPLIT)       // 1024
#define TILES_PER_CTA (KVCHUNK / TN)    // 8
#define NT 128                  // 4 warps

#define SWZ(x) ((uint32_t)(x) ^ ((((uint32_t)(x)) >> 3) & 0x70u))

// smem: QH[8K] | QL[8K] | V0 hi/lo[32K] | V1 hi/lo[32K] = 80K
#define SM_QH 0
#define SM_QL 8192
#define SM_V  16384
#define SMEM_TOTAL 81920

// prepacked bf16 hi/lo (pairs)
__device__ uint32_t g_qh[(size_t)BATCH * SEQ_Q * HDIM / 2];
__device__ uint32_t g_ql[(size_t)BATCH * SEQ_Q * HDIM / 2];
__device__ uint32_t g_vh[(size_t)BATCH * SEQ_V * HDIM / 2];
__device__ uint32_t g_vl[(size_t)BATCH * SEQ_V * HDIM / 2];
// cross-CTA accumulators
__device__ float g_oacc[(size_t)BATCH * SEQ_Q * HDIM];
__device__ float g_lacc[(size_t)BATCH * SEQ_Q];

static __device__ __forceinline__ uint32_t smem_u32(const void* p) {
    uint32_t a;
    asm("{ .reg .u64 t; cvta.to.shared.u64 t, %1; cvt.u32.u64 %0, t; }" : "=r"(a) : "l"(p));
    return a;
}

// pack (x,y) -> bf16x2 hi word-pair + residual lo pair
static __device__ __forceinline__ void split_pack(float x, float y,
                                                  uint32_t& hi, uint32_t& lo) {
    asm("cvt.rn.bf16x2.f32 %0, %1, %2;" : "=r"(hi) : "f"(y), "f"(x));
    float xh = __uint_as_float(hi << 16);
    float yh = __uint_as_float(hi & 0xFFFF0000u);
    asm("cvt.rn.bf16x2.f32 %0, %1, %2;" : "=r"(lo) : "f"(y - yh), "f"(x - xh));
}

#define CP16(dst, src) \
    asm volatile("cp.async.cg.shared.global [%0], [%1], 16;" :: "r"(dst), "l"(src) : "memory")
#define CP_COMMIT() asm volatile("cp.async.commit_group;" ::: "memory")
#define CP_WAIT0()  asm volatile("cp.async.wait_group 0;" ::: "memory")
#define CP_WAIT1()  asm volatile("cp.async.wait_group 1;" ::: "memory")

#define LDSM4(R, addr) \
    asm volatile("ldmatrix.sync.aligned.m8n8.x4.shared.b16 {%0,%1,%2,%3}, [%4];" \
        : "=r"((R)[0]), "=r"((R)[1]), "=r"((R)[2]), "=r"((R)[3]) : "r"(addr))
#define LDSM4T(R, addr) \
    asm volatile("ldmatrix.sync.aligned.m8n8.x4.trans.shared.b16 {%0,%1,%2,%3}, [%4];" \
        : "=r"((R)[0]), "=r"((R)[1]), "=r"((R)[2]), "=r"((R)[3]) : "r"(addr))

#define MMA16816(C, A, b0_, b1_) \
    asm volatile("mma.sync.aligned.m16n8k16.row.col.f32.bf16.bf16.f32 " \
        "{%0,%1,%2,%3}, {%4,%5,%6,%7}, {%8,%9}, {%0,%1,%2,%3};" \
        : "+f"((C)[0]), "+f"((C)[1]), "+f"((C)[2]), "+f"((C)[3]) \
        : "r"((A)[0]), "r"((A)[1]), "r"((A)[2]), "r"((A)[3]), "r"(b0_), "r"(b1_))

#define REDV2(ptr, a, b) \
    asm volatile("red.global.add.v2.f32 [%0], {%1, %2};" :: "l"(ptr), "f"(a), "f"(b) : "memory")

static __device__ __forceinline__ float ex2f(float x) {
    float r; asm("ex2.approx.f32 %0, %1;" : "=f"(r) : "f"(x)); return r;
}

// ---------------- pre-pass: fp32 -> bf16 hi/lo packed; zero accumulators ----
// Each thread handles TWO float4 slots with all loads front-batched (MLP=4).
#define CVT_HALF ((BATCH * SEQ_Q * HDIM / 4) / 2)     // 131072 float4 per half
__global__ void convert_kernel(const float* __restrict__ Q, const float* __restrict__ V) {
    int i0 = blockIdx.x * blockDim.x + threadIdx.x;   // 0..131071
    int i1 = i0 + CVT_HALF;
    const float L2E = 1.4426950408889634f;

    float4 q0 = ((const float4*)Q)[i0];
    float4 v0 = ((const float4*)V)[i0];
    float4 q1 = ((const float4*)Q)[i1];
    float4 v1 = ((const float4*)V)[i1];

    uint2 h, lo;
    split_pack(q0.x * L2E, q0.y * L2E, h.x, lo.x);
    split_pack(q0.z * L2E, q0.w * L2E, h.y, lo.y);
    ((uint2*)g_qh)[i0] = h;  ((uint2*)g_ql)[i0] = lo;
    split_pack(v0.x, v0.y, h.x, lo.x);
    split_pack(v0.z, v0.w, h.y, lo.y);
    ((uint2*)g_vh)[i0] = h;  ((uint2*)g_vl)[i0] = lo;

    split_pack(q1.x * L2E, q1.y * L2E, h.x, lo.x);
    split_pack(q1.z * L2E, q1.w * L2E, h.y, lo.y);
    ((uint2*)g_qh)[i1] = h;  ((uint2*)g_ql)[i1] = lo;
    split_pack(v1.x, v1.y, h.x, lo.x);
    split_pack(v1.z, v1.w, h.y, lo.y);
    ((uint2*)g_vh)[i1] = h;  ((uint2*)g_vl)[i1] = lo;

    float4 z = make_float4(0.f, 0.f, 0.f, 0.f);
    ((float4*)g_oacc)[i0] = z;
    ((float4*)g_oacc)[i1] = z;
    if (i0 < (BATCH * SEQ_Q) / 4) ((float4*)g_lacc)[i0] = z;
}

// ---------------- main attention kernel ----------------
static __device__ __forceinline__ void load_v_tile(uint32_t sb, int b, int kvrow,
                                                   int buf, int tid) {
    const char* gh = (const char*)g_vh + (size_t)(b * SEQ_V + kvrow) * HDIM * 2;
    const char* gl = (const char*)g_vl + (size_t)(b * SEQ_V + kvrow) * HDIM * 2;
    uint32_t vh = sb + SM_V + buf * 32768;
    uint32_t vl = vh + 16384;
#pragma unroll
    for (int i = 0; i < 8; i++) {
        uint32_t off = (uint32_t)(tid + i * NT) * 16;   // 1024 x 16B = 16KB
        CP16(vh + SWZ(off), gh + off);
        CP16(vl + SWZ(off), gl + off);
    }
}

__global__ __launch_bounds__(NT, 2)
void attn_mma_kernel()
{
    extern __shared__ char smem[];
    const uint32_t sb = smem_u32(smem);
    const int tid = threadIdx.x;
    const int l = tid & 31, w = tid >> 5;
    const int qt = blockIdx.x & 255;     // (b, q64)
    const int kc = blockIdx.x >> 8;      // kv chunk 0..3
    const int b = qt >> 6;
    const int qrow0 = (qt & 63) * TQ;    // within batch
    const int kv0 = kc * KVCHUNK;

    // ---- prologue: Q (hi+lo) + V tile 0
    {
        const char* gqh = (const char*)g_qh + (size_t)(b * SEQ_Q + qrow0) * HDIM * 2;
        const char* gql = (const char*)g_ql + (size_t)(b * SEQ_Q + qrow0) * HDIM * 2;
#pragma unroll
        for (int i = 0; i < 4; i++) {
            uint32_t off = (uint32_t)(tid + i * NT) * 16;   // 512 x 16B = 8KB
            CP16(sb + SM_QH + SWZ(off), gqh + off);
            CP16(sb + SM_QL + SWZ(off), gql + off);
        }
        load_v_tile(sb, b, kv0, 0, tid);
        CP_COMMIT();
        CP_WAIT0();
        __syncthreads();
    }

    // ---- Q A-fragments (per warp: rows w*16..w*16+15)
    uint32_t aqh[4][4], aql[4][4];
    {
        int qrow = w * 16 + (l & 15);
#pragma unroll
        for (int kk = 0; kk < 4; kk++) {
            uint32_t off = SWZ((uint32_t)qrow * 128 + kk * 32 + ((l >> 4) & 1) * 16);
            LDSM4(aqh[kk], sb + SM_QH + off);
            LDSM4(aql[kk], sb + SM_QL + off);
        }
    }

    float oc[8][4];
#pragma unroll
    for (int f = 0; f < 8; f++) { oc[f][0] = oc[f][1] = oc[f][2] = oc[f][3] = 0.f; }
    float lsum0 = 0.f, lsum1 = 0.f;

    for (int t = 0; t < TILES_PER_CTA; t++) {
        __syncthreads();
        if (t + 1 < TILES_PER_CTA) {
            load_v_tile(sb, b, kv0 + (t + 1) * TN, (t + 1) & 1, tid);
            CP_COMMIT();
            CP_WAIT1();
        } else {
            CP_WAIT0();
        }
        __syncthreads();

        const uint32_t vhb = sb + SM_V + (t & 1) * 32768;
        const uint32_t vlb = vhb + 16384;

        // ---- S' = (Q*log2e) . V^T  (bf16x3)
        float sc[16][4];
#pragma unroll
        for (int f = 0; f < 16; f++) { sc[f][0] = sc[f][1] = sc[f][2] = sc[f][3] = 0.f; }

#pragma unroll
        for (int kk = 0; kk < 4; kk++) {
#pragma unroll
            for (int np = 0; np < 8; np++) {
                uint32_t off = SWZ((uint32_t)(16 * np + (l & 7) + ((l >> 4) & 1) * 8) * 128
                                   + kk * 32 + ((l >> 3) & 1) * 16);
                uint32_t bh[4], bl[4];
                LDSM4(bh, vhb + off);
                LDSM4(bl, vlb + off);
                MMA16816(sc[2 * np],     aqh[kk], bh[0], bh[1]);
                MMA16816(sc[2 * np + 1], aqh[kk], bh[2], bh[3]);
                MMA16816(sc[2 * np],     aqh[kk], bl[0], bl[1]);
                MMA16816(sc[2 * np + 1], aqh[kk], bl[2], bl[3]);
                MMA16816(sc[2 * np],     aql[kk], bh[0], bh[1]);
                MMA16816(sc[2 * np + 1], aql[kk], bh[2], bh[3]);
            }
        }

        // ---- softmax: p = 2^(s')  (no max subtraction; |s| bounded)
#pragma unroll
        for (int f = 0; f < 16; f++) {
            sc[f][0] = ex2f(sc[f][0]);
            sc[f][1] = ex2f(sc[f][1]);
            sc[f][2] = ex2f(sc[f][2]);
            sc[f][3] = ex2f(sc[f][3]);
            lsum0 += sc[f][0] + sc[f][1];
            lsum1 += sc[f][2] + sc[f][3];
        }

        // ---- O += P . V  (bf16x3)
#pragma unroll
        for (int kcc = 0; kcc < 8; kcc++) {
            uint32_t ah[4], al[4];
            split_pack(sc[2 * kcc][0],     sc[2 * kcc][1],     ah[0], al[0]);
            split_pack(sc[2 * kcc][2],     sc[2 * kcc][3],     ah[1], al[1]);
            split_pack(sc[2 * kcc + 1][0], sc[2 * kcc + 1][1], ah[2], al[2]);
            split_pack(sc[2 * kcc + 1][2], sc[2 * kcc + 1][3], ah[3], al[3]);
#pragma unroll
            for (int dp = 0; dp < 4; dp++) {
                uint32_t off = SWZ((uint32_t)(16 * kcc + (l & 7) + ((l >> 3) & 1) * 8) * 128
                                   + dp * 32 + ((l >> 4) & 1) * 16);
                uint32_t vh[4], vl[4];
                LDSM4T(vh, vhb + off);
                LDSM4T(vl, vlb + off);
                MMA16816(oc[2 * dp],     ah, vh[0], vh[1]);
                MMA16816(oc[2 * dp + 1], ah, vh[2], vh[3]);
                MMA16816(oc[2 * dp],     ah, vl[0], vl[1]);
                MMA16816(oc[2 * dp + 1], ah, vl[2], vl[3]);
                MMA16816(oc[2 * dp],     al, vh[0], vh[1]);
                MMA16816(oc[2 * dp + 1], al, vh[2], vh[3]);
            }
        }
    }

    // ---- merge partials: row sums + unnormalized O (vector reductions)
    lsum0 += __shfl_xor_sync(0xFFFFFFFFu, lsum0, 1);
    lsum0 += __shfl_xor_sync(0xFFFFFFFFu, lsum0, 2);
    lsum1 += __shfl_xor_sync(0xFFFFFFFFu, lsum1, 1);
    lsum1 += __shfl_xor_sync(0xFFFFFFFFu, lsum1, 2);

    const int row0 = qrow0 + w * 16 + (l >> 2);
    float* oa = g_oacc + ((size_t)b * SEQ_Q + row0) * HDIM;
    float* ob = oa + 8 * HDIM;    // row0 + 8
    const int cb = 2 * (l & 3);
#pragma unroll
    for (int f = 0; f < 8; f++) {
        REDV2(oa + 8 * f + cb, oc[f][0], oc[f][1]);
        REDV2(ob + 8 * f + cb, oc[f][2], oc[f][3]);
    }
    if ((l & 3) == 0) {
        atomicAdd(g_lacc + (size_t)b * SEQ_Q + row0,     lsum0);
        atomicAdd(g_lacc + (size_t)b * SEQ_Q + row0 + 8, lsum1);
    }
}

// ---------------- normalize: O = acc / l  (2 float4 per thread, MLP-batched) ----
#define NRM_HALF ((BATCH * SEQ_Q * HDIM / 4) / 2)     // 131072
__global__ void normalize_kernel(float* __restrict__ O) {
    int i0 = blockIdx.x * blockDim.x + threadIdx.x;
    int i1 = i0 + NRM_HALF;
    float4 v0 = ((const float4*)g_oacc)[i0];
    float4 v1 = ((const float4*)g_oacc)[i1];
    float l0 = g_lacc[i0 >> 4];
    float l1 = g_lacc[i1 >> 4];
    float inv0 = 1.0f / l0;
    float inv1 = 1.0f / l1;
    ((float4*)O)[i0] = make_float4(v0.x * inv0, v0.y * inv0, v0.z * inv0, v0.w * inv0);
    ((float4*)O)[i1] = make_float4(v1.x * inv1, v1.y * inv1, v1.z * inv1, v1.w * inv1);
}

extern "C" void kernel_launch(void* const* d_in, const int* in_sizes, int n_in,
                              void* d_out, int out_size)
{
    const float* Q = (const float*)d_in[0];
    const float* V = (const float*)d_in[1];
    float* O = (float*)d_out;

    convert_kernel<<<CVT_HALF / 256, 256>>>(Q, V);

    cudaFuncSetAttribute(attn_mma_kernel,
                         cudaFuncAttributeMaxDynamicSharedMemorySize, SMEM_TOTAL);
    attn_mma_kernel<<<256 * KVSPLIT, NT, SMEM_TOTAL>>>();

    normalize_kernel<<<NRM_HALF / 256, 256>>>(O);
}